// round 16
// baseline (speedup 1.0000x reference)
#include <cuda_runtime.h>
#include <cuda_fp16.h>
#include <cstdint>

#define SEQ 4096
#define DM 1024
#define MTOT 32768

// ---- scratch (device globals: sanctioned no-alloc workaround) ----
__device__ __half g_Q[(size_t)MTOT * DM];
__device__ __half g_K[(size_t)MTOT * DM];
__device__ __half g_V[(size_t)MTOT * DM];
__device__ __half g_MID[(size_t)MTOT * DM];
__device__ __half g_X[(size_t)MTOT * DM];         // fp16 x
__device__ __half g_W[(size_t)3 * DM * DM];       // fp16 [Wq;Wk;Wv]
__device__ __half g_Wo[(size_t)DM * DM];          // fp16 Wo

// ---------------------------------------------------------------------------
// helpers
// ---------------------------------------------------------------------------
__device__ __forceinline__ uint32_t smem_u32(const void* p) {
    uint32_t a;
    asm("{ .reg .u64 t; cvta.to.shared.u64 t, %1; cvt.u32.u64 %0, t; }" : "=r"(a) : "l"(p));
    return a;
}
__device__ __forceinline__ void cpasync16(uint32_t dst, const void* src) {
    asm volatile("cp.async.cg.shared.global [%0], [%1], 16;" :: "r"(dst), "l"(src) : "memory");
}
__device__ __forceinline__ void ldsm4(uint32_t* r, uint32_t addr) {
    asm volatile("ldmatrix.sync.aligned.m8n8.x4.shared.b16 {%0,%1,%2,%3}, [%4];"
                 : "=r"(r[0]), "=r"(r[1]), "=r"(r[2]), "=r"(r[3]) : "r"(addr));
}
__device__ __forceinline__ void ldsm4t(uint32_t* r, uint32_t addr) {
    asm volatile("ldmatrix.sync.aligned.m8n8.x4.trans.shared.b16 {%0,%1,%2,%3}, [%4];"
                 : "=r"(r[0]), "=r"(r[1]), "=r"(r[2]), "=r"(r[3]) : "r"(addr));
}
__device__ __forceinline__ void mma_f16(float* c, const uint32_t* a, const uint32_t* b) {
    asm volatile(
        "mma.sync.aligned.m16n8k16.row.col.f32.f16.f16.f32 "
        "{%0,%1,%2,%3}, {%4,%5,%6,%7}, {%8,%9}, {%0,%1,%2,%3};\n"
        : "+f"(c[0]), "+f"(c[1]), "+f"(c[2]), "+f"(c[3])
        : "r"(a[0]), "r"(a[1]), "r"(a[2]), "r"(a[3]), "r"(b[0]), "r"(b[1]));
}

#define MBAR_INIT(addr, cnt) \
    asm volatile("mbarrier.init.shared.b64 [%0], %1;" :: "r"(addr), "r"(cnt) : "memory")

#define MBAR_ARRIVE_CP(addr) \
    asm volatile("cp.async.mbarrier.arrive.noinc.shared::cta.b64 [%0];" :: "r"(addr) : "memory")

#define MBAR_WAIT(addr, par) do {                                             \
    uint32_t _m = (addr), _p = (par), _d;                                     \
    asm volatile("{ .reg .pred p; mbarrier.try_wait.parity.acquire.cta.shared::cta.b64 p, [%1], %2; selp.b32 %0,1,0,p; }" \
                 : "=r"(_d) : "r"(_m), "r"(_p) : "memory");                   \
    if (!_d) {                                                                \
        asm volatile("{ .reg .pred P1; WL%=: mbarrier.try_wait.parity.acquire.cta.shared::cta.b64 P1, [%0], %1, 0x989680; @P1 bra.uni WD%=; bra.uni WL%=; WD%=: }" \
                     :: "r"(_m), "r"(_p) : "memory");                         \
    } } while (0)

// ---------------------------------------------------------------------------
// fp32 -> fp16 convert, ILP-4 (unchanged)
// ---------------------------------------------------------------------------
#define CVT_STRIDE 1179648

__global__ void __launch_bounds__(256) cvt_all(
    const float4* __restrict__ x,
    const float4* __restrict__ w0, const float4* __restrict__ w1,
    const float4* __restrict__ w2, const float4* __restrict__ w3,
    uint4* __restrict__ dX, uint4* __restrict__ dW, uint4* __restrict__ dWo) {
    const int t0 = blockIdx.x * 256 + threadIdx.x;
    const float4* s[4];
    uint4* d[4];
#pragma unroll
    for (int u = 0; u < 4; u++) {
        const int i = t0 + u * CVT_STRIDE;
        if (i < 4194304) {
            s[u] = x + 2 * (size_t)i;
            d[u] = dX + i;
        } else {
            const int j = i - 4194304;
            const int seg = j >> 17;
            const int t = j & 131071;
            const float4* w = (seg == 0) ? w0 : (seg == 1) ? w1
                              : (seg == 2) ? w2 : w3;
            s[u] = w + 2 * (size_t)t;
            d[u] = (seg < 3) ? (dW + (size_t)seg * 131072 + t) : (dWo + t);
        }
    }
    float4 a[4], b[4];
#pragma unroll
    for (int u = 0; u < 4; u++) { a[u] = s[u][0]; b[u] = s[u][1]; }
#pragma unroll
    for (int u = 0; u < 4; u++) {
        uint4 o;
        *(__half2*)&o.x = __floats2half2_rn(a[u].x, a[u].y);
        *(__half2*)&o.y = __floats2half2_rn(a[u].z, a[u].w);
        *(__half2*)&o.z = __floats2half2_rn(b[u].x, b[u].y);
        *(__half2*)&o.w = __floats2half2_rn(b[u].z, b[u].w);
        *d[u] = o;
    }
}

// ---------------------------------------------------------------------------
// fp16 GEMM: tile 128x128, BK=64, XOR swizzle, 4 warps, 64x64 warp tiles,
// 3-stage cp.async, 2 CTA/SM.
// R16: per-stage mbarriers (count=128, cp.async.mbarrier.arrive.noinc)
// certify stage readiness GLOBALLY without a block barrier -> the kk=3
// cross-iteration prefetch of stage ks+1's kk=0 fragments is now sound
// (this was the R15 race: wait_group is per-thread only). One __syncthreads
// per iteration remains solely for slot-overwrite protection.
// ---------------------------------------------------------------------------
#define AB_BYTES 16384
#define STAGE_BYTES (2 * AB_BYTES)
#define NST 3
#define GSMEM (NST * STAGE_BYTES)
#define EPI_PITCH_H 144

template <int MODE>
__global__ void __launch_bounds__(128, 2) gemm_h(const float* __restrict__ bias,
                                                 float* __restrict__ Cout) {
    extern __shared__ uint8_t sm_raw[];
    __shared__ __align__(8) uint64_t mbar[NST];
    const uint32_t sb = smem_u32(sm_raw);
    const uint32_t mb = smem_u32(mbar);
    const int tid = threadIdx.x;
    const int lane = tid & 31;
    const int wid = tid >> 5;
    const int wm = wid >> 1;
    const int wn = wid & 1;

    const int m0 = blockIdx.y * 128;
    const int n0 = blockIdx.x * 128;
    const __half* A = (MODE == 0) ? g_X : g_MID;
    const __half* B = (MODE == 0) ? g_W : g_Wo;
    const __half* Ag = A + (size_t)m0 * DM;
    const __half* Bg = B + (size_t)n0 * DM;

    if (tid == 0) {
#pragma unroll
        for (int s = 0; s < NST; s++) MBAR_INIT(mb + s * 8, 128);
    }

    int srow[8], ssw[8];
#pragma unroll
    for (int i = 0; i < 8; i++) {
        int id = tid + i * 128;
        int r = id >> 3, c = id & 7;
        srow[i] = r;
        ssw[i] = r * 128 + ((c ^ (r & 7)) << 4);
    }
    const int scol8 = (tid & 7) * 8;

    uint32_t aOff[4]; int aSw[4];
    const int aHi = lane >> 4;
#pragma unroll
    for (int mt = 0; mt < 4; mt++) {
        int r = wm * 64 + mt * 16 + (lane & 15);
        aOff[mt] = r * 128;
        aSw[mt] = r & 7;
    }
    uint32_t bOff[4]; int bSw[4];
    const int bHi = (lane >> 3) & 1;
#pragma unroll
    for (int np = 0; np < 4; np++) {
        int r = wn * 64 + np * 16 + ((lane >> 4) << 3) + (lane & 7);
        bOff[np] = AB_BYTES + r * 128;
        bSw[np] = r & 7;
    }

    float acc[4][8][4];
#pragma unroll
    for (int mt = 0; mt < 4; mt++)
#pragma unroll
        for (int nt = 0; nt < 8; nt++)
#pragma unroll
            for (int i = 0; i < 4; i++) acc[mt][nt][i] = 0.f;

    __syncthreads();   // mbarrier init visible before any arrives

    // ---- prologue: stages 0,1 (arrive on their mbarriers) ----
#pragma unroll
    for (int s = 0; s < NST - 1; s++) {
        const uint32_t st = sb + s * STAGE_BYTES;
        const __half* a = Ag + s * 64;
        const __half* b = Bg + s * 64;
#pragma unroll
        for (int i = 0; i < 8; i++) {
            cpasync16(st + ssw[i], a + (size_t)srow[i] * DM + scol8);
            cpasync16(st + AB_BYTES + ssw[i], b + (size_t)srow[i] * DM + scol8);
        }
        MBAR_ARRIVE_CP(mb + s * 8);
    }

    uint32_t af[2][4][4], bf[2][4][4];

    // stage 0 globally certified -> preload kk=0 fragments
    MBAR_WAIT(mb, 0);
#pragma unroll
    for (int mt = 0; mt < 4; mt++)
        ldsm4(af[0][mt], sb + aOff[mt] + ((aHi ^ aSw[mt]) << 4));
#pragma unroll
    for (int np = 0; np < 4; np++)
        ldsm4(bf[0][np], sb + bOff[np] + ((bHi ^ bSw[np]) << 4));

#pragma unroll 1
    for (int ks = 0; ks < 16; ks++) {
        // protect slot (ks+2)%3 (holds stage ks-1, fully read last iteration)
        __syncthreads();

        if (ks + NST - 1 < 16) {
            const int s = ks + NST - 1;
            const uint32_t stw = sb + (s % NST) * STAGE_BYTES;
            const __half* a = Ag + s * 64;
            const __half* b = Bg + s * 64;
#pragma unroll
            for (int i = 0; i < 8; i++) {
                cpasync16(stw + ssw[i], a + (size_t)srow[i] * DM + scol8);
                cpasync16(stw + AB_BYTES + ssw[i], b + (size_t)srow[i] * DM + scol8);
            }
            MBAR_ARRIVE_CP(mb + (s % NST) * 8);
        }

        const uint32_t st = sb + (ks % NST) * STAGE_BYTES;
        const uint32_t stn = sb + ((ks + 1) % NST) * STAGE_BYTES;

#pragma unroll
        for (int kk = 0; kk < 4; kk++) {
            const int cur = kk & 1, nxt = cur ^ 1;
            if (kk < 3) {          // prefetch kk+1 of this stage (certified)
#pragma unroll
                for (int mt = 0; mt < 4; mt++)
                    ldsm4(af[nxt][mt],
                          st + aOff[mt] + ((((kk + 1) * 2 + aHi) ^ aSw[mt]) << 4));
#pragma unroll
                for (int np = 0; np < 4; np++)
                    ldsm4(bf[nxt][np],
                          st + bOff[np] + ((((kk + 1) * 2 + bHi) ^ bSw[np]) << 4));
            } else if (ks < 15) {  // cross-iteration: certify stage ks+1, then prefetch
                MBAR_WAIT(mb + ((ks + 1) % NST) * 8, ((ks + 1) / NST) & 1);
#pragma unroll
                for (int mt = 0; mt < 4; mt++)
                    ldsm4(af[nxt][mt], stn + aOff[mt] + ((aHi ^ aSw[mt]) << 4));
#pragma unroll
                for (int np = 0; np < 4; np++)
                    ldsm4(bf[nxt][np], stn + bOff[np] + ((bHi ^ bSw[np]) << 4));
            }
#pragma unroll
            for (int mt = 0; mt < 4; mt++)
#pragma unroll
                for (int nt = 0; nt < 8; nt++)
                    mma_f16(acc[mt][nt], af[cur][mt], &bf[cur][nt >> 1][(nt & 1) * 2]);
        }
    }

    // ---- epilogue ----
    const int rq = lane >> 2, q2 = 2 * (lane & 3);
    if (MODE == 0) {
        __syncthreads();   // all warps done reading stages before smem reuse

        __half* Cb = (n0 < 1024) ? g_Q : (n0 < 2048) ? g_K : g_V;
        const int gc0 = (n0 & 1023) + wn * 64;
        const int gr0 = m0 + wm * 64;
        const uint32_t ebo = wid * (64 * EPI_PITCH_H);
#pragma unroll
        for (int mt = 0; mt < 4; mt++) {
            const int r = mt * 16 + rq;
#pragma unroll
            for (int nt = 0; nt < 8; nt++) {
                const int cb = (nt * 8 + q2) * 2;
                *(__half2*)(sm_raw + ebo + r * EPI_PITCH_H + cb) =
                    __floats2half2_rn(acc[mt][nt][0], acc[mt][nt][1]);
                *(__half2*)(sm_raw + ebo + (r + 8) * EPI_PITCH_H + cb) =
                    __floats2half2_rn(acc[mt][nt][2], acc[mt][nt][3]);
            }
        }
        __syncwarp();
#pragma unroll
        for (int it = 0; it < 16; it++) {
            const int id = it * 32 + lane;
            const int r = id >> 3, c = id & 7;
            uint4 v = *(const uint4*)(sm_raw + ebo + r * EPI_PITCH_H + c * 16);
            *(uint4*)&Cb[(size_t)(gr0 + r) * DM + gc0 + c * 8] = v;
        }
    } else {
        const int col0 = n0 + wn * 64;
#pragma unroll
        for (int mt = 0; mt < 4; mt++) {
            const int r = m0 + wm * 64 + mt * 16 + rq;
#pragma unroll
            for (int nt = 0; nt < 8; nt++) {
                const int c = col0 + nt * 8 + q2;
                const float b0 = bias[c], b1 = bias[c + 1];
                *(float2*)&Cout[(size_t)r * DM + c] =
                    make_float2(acc[mt][nt][0] + b0, acc[mt][nt][1] + b1);
                *(float2*)&Cout[(size_t)(r + 8) * DM + c] =
                    make_float2(acc[mt][nt][2] + b0, acc[mt][nt][3] + b1);
            }
        }
    }
}

// ---------------------------------------------------------------------------
// Attention-over-heads on tensor cores (unchanged from R14).
// ---------------------------------------------------------------------------
#define APITCH 144
#define AMAT (16 * APITCH)
#define TOKB (3 * AMAT)
#define ATT_SMEM (4 * 2 * TOKB)

__device__ __forceinline__ void attn_token(uint8_t* tb, int p, int lane) {
    const uint32_t qs = smem_u32(tb);
    const uint32_t ks = qs + AMAT;
    const uint32_t vs = ks + AMAT;

    const uint32_t aAddr = qs + (lane & 15) * APITCH + (lane >> 4) * 16;
    const uint32_t bAddr = ks + (((lane >> 4) << 3) + (lane & 7)) * APITCH +
                           ((lane >> 3) & 1) * 16;
    float S0[4] = {0.f, 0.f, 0.f, 0.f}, S1[4] = {0.f, 0.f, 0.f, 0.f};
#pragma unroll
    for (int kc = 0; kc < 4; kc++) {
        uint32_t aq[4], bk[4];
        ldsm4(aq, aAddr + kc * 32);
        ldsm4(bk, bAddr + kc * 32);
        mma_f16(S0, aq, bk);
        mma_f16(S1, aq, bk + 2);
    }

    float r0[4] = {S0[0] * 0.125f, S0[1] * 0.125f, S1[0] * 0.125f, S1[1] * 0.125f};
    float r1[4] = {S0[2] * 0.125f, S0[3] * 0.125f, S1[2] * 0.125f, S1[3] * 0.125f};
    float m0 = fmaxf(fmaxf(r0[0], r0[1]), fmaxf(r0[2], r0[3]));
    float m1 = fmaxf(fmaxf(r1[0], r1[1]), fmaxf(r1[2], r1[3]));
    m0 = fmaxf(m0, __shfl_xor_sync(0xffffffffu, m0, 1));
    m0 = fmaxf(m0, __shfl_xor_sync(0xffffffffu, m0, 2));
    m1 = fmaxf(m1, __shfl_xor_sync(0xffffffffu, m1, 1));
    m1 = fmaxf(m1, __shfl_xor_sync(0xffffffffu, m1, 2));
    float s0 = 0.f, s1 = 0.f;
#pragma unroll
    for (int i = 0; i < 4; i++) {
        r0[i] = __expf(r0[i] - m0); s0 += r0[i];
        r1[i] = __expf(r1[i] - m1); s1 += r1[i];
    }
    s0 += __shfl_xor_sync(0xffffffffu, s0, 1);
    s0 += __shfl_xor_sync(0xffffffffu, s0, 2);
    s1 += __shfl_xor_sync(0xffffffffu, s1, 1);
    s1 += __shfl_xor_sync(0xffffffffu, s1, 2);
    const float i0 = 1.f / s0, i1 = 1.f / s1;

    uint32_t pa[4];
    *(__half2*)&pa[0] = __floats2half2_rn(r0[0] * i0, r0[1] * i0);
    *(__half2*)&pa[1] = __floats2half2_rn(r1[0] * i1, r1[1] * i1);
    *(__half2*)&pa[2] = __floats2half2_rn(r0[2] * i0, r0[3] * i0);
    *(__half2*)&pa[3] = __floats2half2_rn(r1[2] * i1, r1[3] * i1);

    const uint32_t vAddr = vs + (lane & 15) * APITCH + (lane >> 4) * 16;
    float O[8][4];
#pragma unroll
    for (int nt = 0; nt < 8; nt++)
#pragma unroll
        for (int i = 0; i < 4; i++) O[nt][i] = 0.f;
#pragma unroll
    for (int g = 0; g < 4; g++) {
        uint32_t bv[4];
        ldsm4t(bv, vAddr + g * 32);
        mma_f16(O[2 * g], pa, bv);
        mma_f16(O[2 * g + 1], pa, bv + 2);
    }

    const int rq = lane >> 2, q2 = 2 * (lane & 3);
    __syncwarp();
#pragma unroll
    for (int nt = 0; nt < 8; nt++) {
        const int cb = (nt * 8 + q2) * 2;
        *(__half2*)(tb + rq * APITCH + cb) = __floats2half2_rn(O[nt][0], O[nt][1]);
        *(__half2*)(tb + (rq + 8) * APITCH + cb) = __floats2half2_rn(O[nt][2], O[nt][3]);
    }
    __syncwarp();

    const int n = p >> 12;
    const int s = p & 4095;
    const size_t ob = (size_t)n * SEQ * DM + (size_t)(s >> 4) * DM +
                      (size_t)(s & 15) * 64;
#pragma unroll
    for (int it = 0; it < 4; it++) {
        const int id = it * 32 + lane;
        const int r = id >> 3, c = id & 7;
        uint4 v = *(const uint4*)(tb + r * APITCH + c * 16);
        *(uint4*)&g_MID[ob + (size_t)r * 256 * DM + c * 8] = v;
    }
}

__global__ void __launch_bounds__(128) attn_k() {
    extern __shared__ __align__(16) uint8_t asm_raw[];
    const int lane = threadIdx.x & 31;
    const int w = threadIdx.x >> 5;
    const int p0 = blockIdx.x * 8 + w * 2;
    uint8_t* base = asm_raw + w * 2 * TOKB;

#pragma unroll
    for (int t = 0; t < 2; t++) {
        const __half* q = g_Q + (size_t)(p0 + t) * DM;
        const __half* k = g_K + (size_t)(p0 + t) * DM;
        const __half* v = g_V + (size_t)(p0 + t) * DM;
        const uint32_t qs = smem_u32(base + t * TOKB);
#pragma unroll
        for (int it = 0; it < 4; it++) {
            const int id = lane + it * 32;
            const int r = id >> 3, c = id & 7;
            const int dst = r * APITCH + c * 16;
            const int src = r * 64 + c * 8;
            cpasync16(qs + dst, q + src);
            cpasync16(qs + AMAT + dst, k + src);
            cpasync16(qs + 2 * AMAT + dst, v + src);
        }
        asm volatile("cp.async.commit_group;" ::: "memory");
    }

    asm volatile("cp.async.wait_group 1;" ::: "memory");
    __syncwarp();
    attn_token(base, p0, lane);

    asm volatile("cp.async.wait_group 0;" ::: "memory");
    __syncwarp();
    attn_token(base + TOKB, p0 + 1, lane);
}

extern "C" void kernel_launch(void* const* d_in, const int* in_sizes, int n_in,
                              void* d_out, int out_size) {
    (void)in_sizes; (void)n_in; (void)out_size;
    const float* x  = (const float*)d_in[0];
    const float* Wq = (const float*)d_in[1];
    const float* Wk = (const float*)d_in[2];
    const float* Wv = (const float*)d_in[3];
    const float* Wo = (const float*)d_in[4];
    const float* bo = (const float*)d_in[5];
    float* out = (float*)d_out;

    cudaFuncSetAttribute(gemm_h<0>, cudaFuncAttributeMaxDynamicSharedMemorySize, GSMEM);
    cudaFuncSetAttribute(gemm_h<1>, cudaFuncAttributeMaxDynamicSharedMemorySize, GSMEM);
    cudaFuncSetAttribute(attn_k, cudaFuncAttributeMaxDynamicSharedMemorySize, ATT_SMEM);

    __half* gX; __half* gW; __half* gWo;
    cudaGetSymbolAddress((void**)&gX, g_X);
    cudaGetSymbolAddress((void**)&gW, g_W);
    cudaGetSymbolAddress((void**)&gWo, g_Wo);

    cvt_all<<<CVT_STRIDE / 256, 256>>>(
        (const float4*)x, (const float4*)Wq, (const float4*)Wk,
        (const float4*)Wv, (const float4*)Wo,
        (uint4*)gX, (uint4*)gW, (uint4*)gWo);

    gemm_h<0><<<dim3(24, 256), 128, GSMEM>>>(nullptr, nullptr);
    attn_k<<<MTOT / 8, 128, ATT_SMEM>>>();
    gemm_h<1><<<dim3(8, 256), 128, GSMEM>>>(bo, out);
}

// round 17
// speedup vs baseline: 1.0643x; 1.0643x over previous
#include <cuda_runtime.h>
#include <cuda_fp16.h>
#include <cstdint>

#define SEQ 4096
#define DM 1024
#define MTOT 32768

// ---- scratch (device globals: sanctioned no-alloc workaround) ----
__device__ __half g_Q[(size_t)MTOT * DM];
__device__ __half g_K[(size_t)MTOT * DM];
__device__ __half g_V[(size_t)MTOT * DM];
__device__ __half g_MID[(size_t)MTOT * DM];
__device__ __half g_X[(size_t)MTOT * DM];         // fp16 x
__device__ __half g_W[(size_t)3 * DM * DM];       // fp16 [Wq;Wk;Wv]
__device__ __half g_Wo[(size_t)DM * DM];          // fp16 Wo

// ---------------------------------------------------------------------------
// helpers
// ---------------------------------------------------------------------------
__device__ __forceinline__ uint32_t smem_u32(const void* p) {
    uint32_t a;
    asm("{ .reg .u64 t; cvta.to.shared.u64 t, %1; cvt.u32.u64 %0, t; }" : "=r"(a) : "l"(p));
    return a;
}
__device__ __forceinline__ void cpasync16(uint32_t dst, const void* src) {
    asm volatile("cp.async.cg.shared.global [%0], [%1], 16;" :: "r"(dst), "l"(src) : "memory");
}
__device__ __forceinline__ void ldsm4(uint32_t* r, uint32_t addr) {
    asm volatile("ldmatrix.sync.aligned.m8n8.x4.shared.b16 {%0,%1,%2,%3}, [%4];"
                 : "=r"(r[0]), "=r"(r[1]), "=r"(r[2]), "=r"(r[3]) : "r"(addr));
}
__device__ __forceinline__ void ldsm4t(uint32_t* r, uint32_t addr) {
    asm volatile("ldmatrix.sync.aligned.m8n8.x4.trans.shared.b16 {%0,%1,%2,%3}, [%4];"
                 : "=r"(r[0]), "=r"(r[1]), "=r"(r[2]), "=r"(r[3]) : "r"(addr));
}
__device__ __forceinline__ void mma_f16(float* c, const uint32_t* a, const uint32_t* b) {
    asm volatile(
        "mma.sync.aligned.m16n8k16.row.col.f32.f16.f16.f32 "
        "{%0,%1,%2,%3}, {%4,%5,%6,%7}, {%8,%9}, {%0,%1,%2,%3};\n"
        : "+f"(c[0]), "+f"(c[1]), "+f"(c[2]), "+f"(c[3])
        : "r"(a[0]), "r"(a[1]), "r"(a[2]), "r"(a[3]), "r"(b[0]), "r"(b[1]));
}

// ---------------------------------------------------------------------------
// fp32 -> fp16 convert, ILP-4 (unchanged)
// ---------------------------------------------------------------------------
#define CVT_STRIDE 1179648

__global__ void __launch_bounds__(256) cvt_all(
    const float4* __restrict__ x,
    const float4* __restrict__ w0, const float4* __restrict__ w1,
    const float4* __restrict__ w2, const float4* __restrict__ w3,
    uint4* __restrict__ dX, uint4* __restrict__ dW, uint4* __restrict__ dWo) {
    const int t0 = blockIdx.x * 256 + threadIdx.x;
    const float4* s[4];
    uint4* d[4];
#pragma unroll
    for (int u = 0; u < 4; u++) {
        const int i = t0 + u * CVT_STRIDE;
        if (i < 4194304) {
            s[u] = x + 2 * (size_t)i;
            d[u] = dX + i;
        } else {
            const int j = i - 4194304;
            const int seg = j >> 17;
            const int t = j & 131071;
            const float4* w = (seg == 0) ? w0 : (seg == 1) ? w1
                              : (seg == 2) ? w2 : w3;
            s[u] = w + 2 * (size_t)t;
            d[u] = (seg < 3) ? (dW + (size_t)seg * 131072 + t) : (dWo + t);
        }
    }
    float4 a[4], b[4];
#pragma unroll
    for (int u = 0; u < 4; u++) { a[u] = s[u][0]; b[u] = s[u][1]; }
#pragma unroll
    for (int u = 0; u < 4; u++) {
        uint4 o;
        *(__half2*)&o.x = __floats2half2_rn(a[u].x, a[u].y);
        *(__half2*)&o.y = __floats2half2_rn(a[u].z, a[u].w);
        *(__half2*)&o.z = __floats2half2_rn(b[u].x, b[u].y);
        *(__half2*)&o.w = __floats2half2_rn(b[u].z, b[u].w);
        *d[u] = o;
    }
}

// ---------------------------------------------------------------------------
// fp16 GEMM: tile 128x128, BK=64, XOR swizzle, 4 warps, 64x64 warp tiles,
// 3-stage cp.async, reg double-buffered fragments, 2 CTA/SM.
// R17 (on the R14 baseline): the 16 cp.async issues per iteration are spread
// across the 4 kk bursts (4 per burst, after that burst's ldsm prefetch) so
// LDGSTS issue bursts don't head-of-line block fragment LDSMs in the MIO
// queue. Synchronization contract identical to R14 (one commit per
// iteration at loop end; wait_group 1 + __syncthreads at loop top).
// ---------------------------------------------------------------------------
#define AB_BYTES 16384
#define STAGE_BYTES (2 * AB_BYTES)
#define NST 3
#define GSMEM (NST * STAGE_BYTES)
#define EPI_PITCH_H 144

template <int MODE>
__global__ void __launch_bounds__(128, 2) gemm_h(const float* __restrict__ bias,
                                                 float* __restrict__ Cout) {
    extern __shared__ uint8_t sm_raw[];
    const uint32_t sb = smem_u32(sm_raw);
    const int tid = threadIdx.x;
    const int lane = tid & 31;
    const int wid = tid >> 5;
    const int wm = wid >> 1;
    const int wn = wid & 1;

    const int m0 = blockIdx.y * 128;
    const int n0 = blockIdx.x * 128;
    const __half* A = (MODE == 0) ? g_X : g_MID;
    const __half* B = (MODE == 0) ? g_W : g_Wo;
    const __half* Ag = A + (size_t)m0 * DM;
    const __half* Bg = B + (size_t)n0 * DM;

    int srow[8], ssw[8];
#pragma unroll
    for (int i = 0; i < 8; i++) {
        int id = tid + i * 128;
        int r = id >> 3, c = id & 7;
        srow[i] = r;
        ssw[i] = r * 128 + ((c ^ (r & 7)) << 4);
    }
    const int scol8 = (tid & 7) * 8;

    uint32_t aOff[4]; int aSw[4];
    const int aHi = lane >> 4;
#pragma unroll
    for (int mt = 0; mt < 4; mt++) {
        int r = wm * 64 + mt * 16 + (lane & 15);
        aOff[mt] = r * 128;
        aSw[mt] = r & 7;
    }
    uint32_t bOff[4]; int bSw[4];
    const int bHi = (lane >> 3) & 1;
#pragma unroll
    for (int np = 0; np < 4; np++) {
        int r = wn * 64 + np * 16 + ((lane >> 4) << 3) + (lane & 7);
        bOff[np] = AB_BYTES + r * 128;
        bSw[np] = r & 7;
    }

    float acc[4][8][4];
#pragma unroll
    for (int mt = 0; mt < 4; mt++)
#pragma unroll
        for (int nt = 0; nt < 8; nt++)
#pragma unroll
            for (int i = 0; i < 4; i++) acc[mt][nt][i] = 0.f;

    // ---- prologue: stages 0,1 ----
#pragma unroll
    for (int s = 0; s < NST - 1; s++) {
        const uint32_t st = sb + s * STAGE_BYTES;
        const __half* a = Ag + s * 64;
        const __half* b = Bg + s * 64;
#pragma unroll
        for (int i = 0; i < 8; i++) {
            cpasync16(st + ssw[i], a + (size_t)srow[i] * DM + scol8);
            cpasync16(st + AB_BYTES + ssw[i], b + (size_t)srow[i] * DM + scol8);
        }
        asm volatile("cp.async.commit_group;" ::: "memory");
    }

    uint32_t af[2][4][4], bf[2][4][4];

#pragma unroll 1
    for (int ks = 0; ks < 16; ks++) {
        asm volatile("cp.async.wait_group 1;" ::: "memory");
        __syncthreads();

        const uint32_t st = sb + (ks % NST) * STAGE_BYTES;

        // fragments for kk=0 FIRST (tensor work starts immediately)
#pragma unroll
        for (int mt = 0; mt < 4; mt++)
            ldsm4(af[0][mt], st + aOff[mt] + ((aHi ^ aSw[mt]) << 4));
#pragma unroll
        for (int np = 0; np < 4; np++)
            ldsm4(bf[0][np], st + bOff[np] + ((bHi ^ bSw[np]) << 4));

        const int sNext = ks + NST - 1;
        const bool doIssue = sNext < 16;
        const uint32_t stw = sb + (sNext % NST) * STAGE_BYTES;
        const __half* aN = Ag + sNext * 64;
        const __half* bN = Bg + sNext * 64;

#pragma unroll
        for (int kk = 0; kk < 4; kk++) {
            const int cur = kk & 1, nxt = cur ^ 1;
            if (kk < 3) {   // prefetch kk+1 fragments under this burst's MMAs
#pragma unroll
                for (int mt = 0; mt < 4; mt++)
                    ldsm4(af[nxt][mt],
                          st + aOff[mt] + ((((kk + 1) * 2 + aHi) ^ aSw[mt]) << 4));
#pragma unroll
                for (int np = 0; np < 4; np++)
                    ldsm4(bf[nxt][np],
                          st + bOff[np] + ((((kk + 1) * 2 + bHi) ^ bSw[np]) << 4));
            }
            // smooth MIO: 4 of the 16 LDGSTS per burst, after the ldsm prefetch
            if (doIssue) {
#pragma unroll
                for (int i = 2 * kk; i < 2 * kk + 2; i++) {
                    cpasync16(stw + ssw[i], aN + (size_t)srow[i] * DM + scol8);
                    cpasync16(stw + AB_BYTES + ssw[i], bN + (size_t)srow[i] * DM + scol8);
                }
            }
#pragma unroll
            for (int mt = 0; mt < 4; mt++)
#pragma unroll
                for (int nt = 0; nt < 8; nt++)
                    mma_f16(acc[mt][nt], af[cur][mt], &bf[cur][nt >> 1][(nt & 1) * 2]);
        }
        asm volatile("cp.async.commit_group;" ::: "memory");
    }

    // ---- epilogue ----
    const int rq = lane >> 2, q2 = 2 * (lane & 3);
    if (MODE == 0) {
        asm volatile("cp.async.wait_group 0;" ::: "memory");
        __syncthreads();

        __half* Cb = (n0 < 1024) ? g_Q : (n0 < 2048) ? g_K : g_V;
        const int gc0 = (n0 & 1023) + wn * 64;
        const int gr0 = m0 + wm * 64;
        const uint32_t ebo = wid * (64 * EPI_PITCH_H);
#pragma unroll
        for (int mt = 0; mt < 4; mt++) {
            const int r = mt * 16 + rq;
#pragma unroll
            for (int nt = 0; nt < 8; nt++) {
                const int cb = (nt * 8 + q2) * 2;
                *(__half2*)(sm_raw + ebo + r * EPI_PITCH_H + cb) =
                    __floats2half2_rn(acc[mt][nt][0], acc[mt][nt][1]);
                *(__half2*)(sm_raw + ebo + (r + 8) * EPI_PITCH_H + cb) =
                    __floats2half2_rn(acc[mt][nt][2], acc[mt][nt][3]);
            }
        }
        __syncwarp();
#pragma unroll
        for (int it = 0; it < 16; it++) {
            const int id = it * 32 + lane;
            const int r = id >> 3, c = id & 7;
            uint4 v = *(const uint4*)(sm_raw + ebo + r * EPI_PITCH_H + c * 16);
            *(uint4*)&Cb[(size_t)(gr0 + r) * DM + gc0 + c * 8] = v;
        }
    } else {
        const int col0 = n0 + wn * 64;
#pragma unroll
        for (int mt = 0; mt < 4; mt++) {
            const int r = m0 + wm * 64 + mt * 16 + rq;
#pragma unroll
            for (int nt = 0; nt < 8; nt++) {
                const int c = col0 + nt * 8 + q2;
                const float b0 = bias[c], b1 = bias[c + 1];
                *(float2*)&Cout[(size_t)r * DM + c] =
                    make_float2(acc[mt][nt][0] + b0, acc[mt][nt][1] + b1);
                *(float2*)&Cout[(size_t)(r + 8) * DM + c] =
                    make_float2(acc[mt][nt][2] + b0, acc[mt][nt][3] + b1);
            }
        }
    }
}

// ---------------------------------------------------------------------------
// Attention-over-heads on tensor cores (unchanged from R14).
// ---------------------------------------------------------------------------
#define APITCH 144
#define AMAT (16 * APITCH)
#define TOKB (3 * AMAT)
#define ATT_SMEM (4 * 2 * TOKB)

__device__ __forceinline__ void attn_token(uint8_t* tb, int p, int lane) {
    const uint32_t qs = smem_u32(tb);
    const uint32_t ks = qs + AMAT;
    const uint32_t vs = ks + AMAT;

    const uint32_t aAddr = qs + (lane & 15) * APITCH + (lane >> 4) * 16;
    const uint32_t bAddr = ks + (((lane >> 4) << 3) + (lane & 7)) * APITCH +
                           ((lane >> 3) & 1) * 16;
    float S0[4] = {0.f, 0.f, 0.f, 0.f}, S1[4] = {0.f, 0.f, 0.f, 0.f};
#pragma unroll
    for (int kc = 0; kc < 4; kc++) {
        uint32_t aq[4], bk[4];
        ldsm4(aq, aAddr + kc * 32);
        ldsm4(bk, bAddr + kc * 32);
        mma_f16(S0, aq, bk);
        mma_f16(S1, aq, bk + 2);
    }

    float r0[4] = {S0[0] * 0.125f, S0[1] * 0.125f, S1[0] * 0.125f, S1[1] * 0.125f};
    float r1[4] = {S0[2] * 0.125f, S0[3] * 0.125f, S1[2] * 0.125f, S1[3] * 0.125f};
    float m0 = fmaxf(fmaxf(r0[0], r0[1]), fmaxf(r0[2], r0[3]));
    float m1 = fmaxf(fmaxf(r1[0], r1[1]), fmaxf(r1[2], r1[3]));
    m0 = fmaxf(m0, __shfl_xor_sync(0xffffffffu, m0, 1));
    m0 = fmaxf(m0, __shfl_xor_sync(0xffffffffu, m0, 2));
    m1 = fmaxf(m1, __shfl_xor_sync(0xffffffffu, m1, 1));
    m1 = fmaxf(m1, __shfl_xor_sync(0xffffffffu, m1, 2));
    float s0 = 0.f, s1 = 0.f;
#pragma unroll
    for (int i = 0; i < 4; i++) {
        r0[i] = __expf(r0[i] - m0); s0 += r0[i];
        r1[i] = __expf(r1[i] - m1); s1 += r1[i];
    }
    s0 += __shfl_xor_sync(0xffffffffu, s0, 1);
    s0 += __shfl_xor_sync(0xffffffffu, s0, 2);
    s1 += __shfl_xor_sync(0xffffffffu, s1, 1);
    s1 += __shfl_xor_sync(0xffffffffu, s1, 2);
    const float i0 = 1.f / s0, i1 = 1.f / s1;

    uint32_t pa[4];
    *(__half2*)&pa[0] = __floats2half2_rn(r0[0] * i0, r0[1] * i0);
    *(__half2*)&pa[1] = __floats2half2_rn(r1[0] * i1, r1[1] * i1);
    *(__half2*)&pa[2] = __floats2half2_rn(r0[2] * i0, r0[3] * i0);
    *(__half2*)&pa[3] = __floats2half2_rn(r1[2] * i1, r1[3] * i1);

    const uint32_t vAddr = vs + (lane & 15) * APITCH + (lane >> 4) * 16;
    float O[8][4];
#pragma unroll
    for (int nt = 0; nt < 8; nt++)
#pragma unroll
        for (int i = 0; i < 4; i++) O[nt][i] = 0.f;
#pragma unroll
    for (int g = 0; g < 4; g++) {
        uint32_t bv[4];
        ldsm4t(bv, vAddr + g * 32);
        mma_f16(O[2 * g], pa, bv);
        mma_f16(O[2 * g + 1], pa, bv + 2);
    }

    const int rq = lane >> 2, q2 = 2 * (lane & 3);
    __syncwarp();
#pragma unroll
    for (int nt = 0; nt < 8; nt++) {
        const int cb = (nt * 8 + q2) * 2;
        *(__half2*)(tb + rq * APITCH + cb) = __floats2half2_rn(O[nt][0], O[nt][1]);
        *(__half2*)(tb + (rq + 8) * APITCH + cb) = __floats2half2_rn(O[nt][2], O[nt][3]);
    }
    __syncwarp();

    const int n = p >> 12;
    const int s = p & 4095;
    const size_t ob = (size_t)n * SEQ * DM + (size_t)(s >> 4) * DM +
                      (size_t)(s & 15) * 64;
#pragma unroll
    for (int it = 0; it < 4; it++) {
        const int id = it * 32 + lane;
        const int r = id >> 3, c = id & 7;
        uint4 v = *(const uint4*)(tb + r * APITCH + c * 16);
        *(uint4*)&g_MID[ob + (size_t)r * 256 * DM + c * 8] = v;
    }
}

__global__ void __launch_bounds__(128) attn_k() {
    extern __shared__ __align__(16) uint8_t asm_raw[];
    const int lane = threadIdx.x & 31;
    const int w = threadIdx.x >> 5;
    const int p0 = blockIdx.x * 8 + w * 2;
    uint8_t* base = asm_raw + w * 2 * TOKB;

#pragma unroll
    for (int t = 0; t < 2; t++) {
        const __half* q = g_Q + (size_t)(p0 + t) * DM;
        const __half* k = g_K + (size_t)(p0 + t) * DM;
        const __half* v = g_V + (size_t)(p0 + t) * DM;
        const uint32_t qs = smem_u32(base + t * TOKB);
#pragma unroll
        for (int it = 0; it < 4; it++) {
            const int id = lane + it * 32;
            const int r = id >> 3, c = id & 7;
            const int dst = r * APITCH + c * 16;
            const int src = r * 64 + c * 8;
            cpasync16(qs + dst, q + src);
            cpasync16(qs + AMAT + dst, k + src);
            cpasync16(qs + 2 * AMAT + dst, v + src);
        }
        asm volatile("cp.async.commit_group;" ::: "memory");
    }

    asm volatile("cp.async.wait_group 1;" ::: "memory");
    __syncwarp();
    attn_token(base, p0, lane);

    asm volatile("cp.async.wait_group 0;" ::: "memory");
    __syncwarp();
    attn_token(base + TOKB, p0 + 1, lane);
}

extern "C" void kernel_launch(void* const* d_in, const int* in_sizes, int n_in,
                              void* d_out, int out_size) {
    (void)in_sizes; (void)n_in; (void)out_size;
    const float* x  = (const float*)d_in[0];
    const float* Wq = (const float*)d_in[1];
    const float* Wk = (const float*)d_in[2];
    const float* Wv = (const float*)d_in[3];
    const float* Wo = (const float*)d_in[4];
    const float* bo = (const float*)d_in[5];
    float* out = (float*)d_out;

    cudaFuncSetAttribute(gemm_h<0>, cudaFuncAttributeMaxDynamicSharedMemorySize, GSMEM);
    cudaFuncSetAttribute(gemm_h<1>, cudaFuncAttributeMaxDynamicSharedMemorySize, GSMEM);
    cudaFuncSetAttribute(attn_k, cudaFuncAttributeMaxDynamicSharedMemorySize, ATT_SMEM);

    __half* gX; __half* gW; __half* gWo;
    cudaGetSymbolAddress((void**)&gX, g_X);
    cudaGetSymbolAddress((void**)&gW, g_W);
    cudaGetSymbolAddress((void**)&gWo, g_Wo);

    cvt_all<<<CVT_STRIDE / 256, 256>>>(
        (const float4*)x, (const float4*)Wq, (const float4*)Wk,
        (const float4*)Wv, (const float4*)Wo,
        (uint4*)gX, (uint4*)gW, (uint4*)gWo);

    gemm_h<0><<<dim3(24, 256), 128, GSMEM>>>(nullptr, nullptr);
    attn_k<<<MTOT / 8, 128, ATT_SMEM>>>();
    gemm_h<1><<<dim3(8, 256), 128, GSMEM>>>(bo, out);
}